// round 7
// baseline (speedup 1.0000x reference)
#include <cuda_runtime.h>
#include <float.h>

#define BATCH 2
#define CH 64
#define H 480
#define W 480
#define HW (H * W)            // 230400
#define HC 960
#define WC 960
#define HWC (HC * WC)         // 921600
#define XQ (W / 4)            // 120
#define PERKIND (BATCH * H * XQ)   // 115200
#define LIST_MAX 32768

// ---------------- device scratch (zero at load; each call restores the
// all-zero state: pool_feat zeroes cen winner cells, fused_out zeroes the
// rest as it reads them — no separate cleanup kernel) ----------------------
// Encoding: winner grids store (point_idx + 1); 0 = empty.
//           pooled grids store (slot + 1);      0 = empty.
__device__ int   g_win_l[BATCH * HW];
__device__ int   g_win_r[BATCH * HW];
__device__ int   g_win_lc[BATCH * HWC];
__device__ int   g_win_rc[BATCH * HWC];
__device__ int   g_pwin_lc[BATCH * HW];
__device__ int   g_pwin_rc[BATCH * HW];
__device__ int   g_list_lc[LIST_MAX];
__device__ int   g_list_rc[LIST_MAX];
__device__ int   g_cnt[2];
__device__ float g_pf_lc[LIST_MAX * CH];     // pooled 64-ch features, compact
__device__ float g_pf_rc[LIST_MAX * CH];

#define CLAIM_TAG 0x7FFFFFFF

// last point index wins == JAX sequential .set semantics
__global__ void scatter_all(const int* __restrict__ cL, int pL,
                            const int* __restrict__ cR, int pR,
                            const int* __restrict__ cLC, int pLC,
                            const int* __restrict__ cRC, int pRC) {
    int i = blockIdx.x * blockDim.x + threadIdx.x;
    if (i < pL) {
        int4 c = __ldg((const int4*)(cL + 4 * i));
        atomicMax(&g_win_l[c.x * HW + c.z * W + c.w], i + 1);
    } else if (i < pL + pR) {
        int j = i - pL;
        int4 c = __ldg((const int4*)(cR + 4 * j));
        atomicMax(&g_win_r[c.x * HW + c.z * W + c.w], j + 1);
    } else if (i < pL + pR + pLC) {
        int j = i - pL - pR;
        int4 c = __ldg((const int4*)(cLC + 4 * j));
        atomicMax(&g_win_lc[c.x * HWC + c.z * WC + c.w], j + 1);
        int cellp = c.x * HW + (c.z >> 1) * W + (c.w >> 1);
        if (atomicCAS(&g_pwin_lc[cellp], 0, CLAIM_TAG) == 0) {
            int e = atomicAdd(&g_cnt[0], 1);
            g_list_lc[e] = cellp;
            g_pwin_lc[cellp] = e + 1;
        }
    } else if (i < pL + pR + pLC + pRC) {
        int j = i - pL - pR - pLC;
        int4 c = __ldg((const int4*)(cRC + 4 * j));
        atomicMax(&g_win_rc[c.x * HWC + c.z * WC + c.w], j + 1);
        int cellp = c.x * HW + (c.z >> 1) * W + (c.w >> 1);
        if (atomicCAS(&g_pwin_rc[cellp], 0, CLAIM_TAG) == 0) {
            int e = atomicAdd(&g_cnt[1], 1);
            g_list_rc[e] = cellp;
            g_pwin_rc[cellp] = e + 1;
        }
    }
}

// one warp per occupied pooled cell: resolve 2x2 max over 64 channels.
// Pool windows partition the cen grid, so after reading its 4 winner cells
// this warp is their sole owner and zeroes them (cleanup folded in).
__global__ void pool_feat(const float* __restrict__ fLC,
                          const float* __restrict__ fRC, int pLC) {
    int g = (blockIdx.x * blockDim.x + threadIdx.x) >> 5;
    int lane = threadIdx.x & 31;
    const float* feat;
    const int* wingrid;
    float* pf;
    int e, cellp;
    if (g < pLC) {
        e = g;
        if (e >= g_cnt[0]) return;
        cellp = g_list_lc[e]; feat = fLC; pf = g_pf_lc; wingrid = g_win_lc;
    } else {
        e = g - pLC;
        if (e >= g_cnt[1]) return;
        cellp = g_list_rc[e]; feat = fRC; pf = g_pf_rc; wingrid = g_win_rc;
    }
    int b = cellp / HW, sp = cellp % HW;
    int yp = sp / W, xp = sp % W;
    const int* winc = wingrid + (size_t)b * HWC + (2 * yp) * WC + 2 * xp;
    int w0 = winc[0], w1 = winc[1], w2 = winc[WC], w3 = winc[WC + 1];
    if (lane == 0) {       // zero the cen winner cells (sole owner)
        int2 z = make_int2(0, 0);
        *(int2*)winc = z;
        *(int2*)(winc + WC) = z;
    }
    bool full = (w0 > 0) && (w1 > 0) && (w2 > 0) && (w3 > 0);
#pragma unroll
    for (int h = 0; h < 2; h++) {
        int c = lane + 32 * h;
        float m = full ? -FLT_MAX : 0.0f;
        if (w0 > 0) m = fmaxf(m, __ldg(&feat[(size_t)(w0 - 1) * CH + c]));
        if (w1 > 0) m = fmaxf(m, __ldg(&feat[(size_t)(w1 - 1) * CH + c]));
        if (w2 > 0) m = fmaxf(m, __ldg(&feat[(size_t)(w2 - 1) * CH + c]));
        if (w3 > 0) m = fmaxf(m, __ldg(&feat[(size_t)(w3 - 1) * CH + c]));
        pf[(size_t)e * CH + c] = m;
    }
}

__global__ void __launch_bounds__(256)
fused_out(const float4* __restrict__ fL4, const float4* __restrict__ fR4,
          float* __restrict__ out) {
    int t = blockIdx.x * blockDim.x + threadIdx.x;
    if (t == 0) { g_cnt[0] = 0; g_cnt[1] = 0; }   // pool_feat already consumed
    int kind = t / PERKIND;          // uniform per block (PERKIND % 256 == 0)
    int u = t % PERKIND;
    int x4 = u % XQ; u /= XQ;
    int y = u % H;
    int b = u / H;
    int s = y * W + 4 * x4;

    const size_t GRID = (size_t)CH * HW;
    const size_t OUT_R = (size_t)BATCH * GRID;
    const size_t OUT_CAT = 2 * OUT_R;
    const float4 z4 = make_float4(0.f, 0.f, 0.f, 0.f);

    const int* win;
    const float4* f4;
    float* o1;
    float* o2 = nullptr;
    float* cat = out + OUT_CAT + (size_t)b * 4 * GRID;
    if (kind == 0) {
        win = g_win_l; f4 = fL4;
        o1 = out + (size_t)b * GRID + s;
        o2 = cat + s;
    } else if (kind == 1) {
        win = g_win_r; f4 = fR4;
        o1 = out + OUT_R + (size_t)b * GRID + s;
        o2 = cat + (size_t)2 * CH * HW + s;
    } else if (kind == 2) {
        win = g_pwin_lc; f4 = (const float4*)g_pf_lc;
        o1 = cat + (size_t)CH * HW + s;
    } else {
        win = g_pwin_rc; f4 = (const float4*)g_pf_rc;
        o1 = cat + (size_t)3 * CH * HW + s;
    }

    int4* wp = (int4*)(win + b * HW + s);     // sole reader of this quad
    int4 w = *wp;
    bool any = (w.x | w.y | w.z | w.w) != 0;
    if (any) *wp = make_int4(0, 0, 0, 0);     // restore zero state (same thread,
                                              // program-ordered after the load)
    // pre-bias so gather index is w*16 directly (values are idx+1)
    const float4* f4b = f4 - 16;

#pragma unroll
    for (int sub = 0; sub < 16; sub++) {
        float4 c0 = z4, c1 = z4, c2 = z4, c3 = z4;
        if (any) {
            if (w.x > 0) c0 = __ldg(&f4b[(size_t)w.x * 16 + sub]);
            if (w.y > 0) c1 = __ldg(&f4b[(size_t)w.y * 16 + sub]);
            if (w.z > 0) c2 = __ldg(&f4b[(size_t)w.z * 16 + sub]);
            if (w.w > 0) c3 = __ldg(&f4b[(size_t)w.w * 16 + sub]);
        }
        float4 v0 = make_float4(c0.x, c1.x, c2.x, c3.x);
        float4 v1 = make_float4(c0.y, c1.y, c2.y, c3.y);
        float4 v2 = make_float4(c0.z, c1.z, c2.z, c3.z);
        float4 v3 = make_float4(c0.w, c1.w, c2.w, c3.w);
        size_t co = (size_t)(sub * 4) * HW;
        __stcs((float4*)(o1 + co), v0);
        __stcs((float4*)(o1 + co + HW), v1);
        __stcs((float4*)(o1 + co + 2 * (size_t)HW), v2);
        __stcs((float4*)(o1 + co + 3 * (size_t)HW), v3);
        if (o2) {
            __stcs((float4*)(o2 + co), v0);
            __stcs((float4*)(o2 + co + HW), v1);
            __stcs((float4*)(o2 + co + 2 * (size_t)HW), v2);
            __stcs((float4*)(o2 + co + 3 * (size_t)HW), v3);
        }
    }
}

extern "C" void kernel_launch(void* const* d_in, const int* in_sizes, int n_in,
                              void* d_out, int out_size) {
    const float* fRC = (const float*)d_in[0];
    const int*   cRC = (const int*)d_in[1];
    const float* fLC = (const float*)d_in[2];
    const int*   cLC = (const int*)d_in[3];
    const float* fL  = (const float*)d_in[4];
    const int*   cL  = (const int*)d_in[5];
    const float* fR  = (const float*)d_in[6];
    const int*   cR  = (const int*)d_in[7];
    float* out = (float*)d_out;

    int pRC = in_sizes[1] / 4;
    int pLC = in_sizes[3] / 4;
    int pL  = in_sizes[5] / 4;
    int pR  = in_sizes[7] / 4;
    int PT = pL + pR + pLC + pRC;

    scatter_all<<<(PT + 255) / 256, 256>>>(cL, pL, cR, pR, cLC, pLC, cRC, pRC);

    int pw = pLC + pRC;  // upper bound on occupied pooled cells (both kinds)
    pool_feat<<<(pw * 32 + 255) / 256, 256>>>(fLC, fRC, pLC);

    fused_out<<<4 * PERKIND / 256, 256>>>((const float4*)fL, (const float4*)fR, out);
}

// round 8
// speedup vs baseline: 1.2557x; 1.2557x over previous
#include <cuda_runtime.h>
#include <float.h>

#define BATCH 2
#define CH 64
#define H 480
#define W 480
#define HW (H * W)            // 230400
#define HC 960
#define WC 960
#define HWC (HC * WC)         // 921600
#define XQ (W / 4)            // 120
#define NCHUNK 2
#define PERKIND (BATCH * NCHUNK * H * XQ)   // 230400
#define LIST_MAX 32768

// ---------------- device scratch (zero at load; each call restores the
// all-zero state: pool_feat zeroes cen winner cells, cleanup_* the rest) ----
// Encoding: winner grids store (point_idx + 1); 0 = empty.
//           pooled grids store (slot + 1);      0 = empty.
__device__ int   g_win_l[BATCH * HW];
__device__ int   g_win_r[BATCH * HW];
__device__ int   g_win_lc[BATCH * HWC];
__device__ int   g_win_rc[BATCH * HWC];
__device__ int   g_pwin_lc[BATCH * HW];
__device__ int   g_pwin_rc[BATCH * HW];
__device__ int   g_list_lc[LIST_MAX];
__device__ int   g_list_rc[LIST_MAX];
__device__ int   g_cnt[2];
__device__ float g_pf_lc[LIST_MAX * CH];     // pooled 64-ch features, compact
__device__ float g_pf_rc[LIST_MAX * CH];

#define CLAIM_TAG 0x7FFFFFFF

// last point index wins == JAX sequential .set semantics
__global__ void scatter_all(const int* __restrict__ cL, int pL,
                            const int* __restrict__ cR, int pR,
                            const int* __restrict__ cLC, int pLC,
                            const int* __restrict__ cRC, int pRC) {
    int i = blockIdx.x * blockDim.x + threadIdx.x;
    if (i < pL) {
        int4 c = __ldg((const int4*)(cL + 4 * i));
        atomicMax(&g_win_l[c.x * HW + c.z * W + c.w], i + 1);
    } else if (i < pL + pR) {
        int j = i - pL;
        int4 c = __ldg((const int4*)(cR + 4 * j));
        atomicMax(&g_win_r[c.x * HW + c.z * W + c.w], j + 1);
    } else if (i < pL + pR + pLC) {
        int j = i - pL - pR;
        int4 c = __ldg((const int4*)(cLC + 4 * j));
        atomicMax(&g_win_lc[c.x * HWC + c.z * WC + c.w], j + 1);
        int cellp = c.x * HW + (c.z >> 1) * W + (c.w >> 1);
        if (atomicCAS(&g_pwin_lc[cellp], 0, CLAIM_TAG) == 0) {
            int e = atomicAdd(&g_cnt[0], 1);
            g_list_lc[e] = cellp;
            g_pwin_lc[cellp] = e + 1;
        }
    } else if (i < pL + pR + pLC + pRC) {
        int j = i - pL - pR - pLC;
        int4 c = __ldg((const int4*)(cRC + 4 * j));
        atomicMax(&g_win_rc[c.x * HWC + c.z * WC + c.w], j + 1);
        int cellp = c.x * HW + (c.z >> 1) * W + (c.w >> 1);
        if (atomicCAS(&g_pwin_rc[cellp], 0, CLAIM_TAG) == 0) {
            int e = atomicAdd(&g_cnt[1], 1);
            g_list_rc[e] = cellp;
            g_pwin_rc[cellp] = e + 1;
        }
    }
}

// one warp per occupied pooled cell: resolve 2x2 max over 64 channels.
// Pool windows partition the cen grid; this warp solely owns its 4 winner
// cells and zeroes them (cen winner-grid cleanup folded in).
__global__ void pool_feat(const float* __restrict__ fLC,
                          const float* __restrict__ fRC, int pLC) {
    int g = (blockIdx.x * blockDim.x + threadIdx.x) >> 5;
    int lane = threadIdx.x & 31;
    const float* feat;
    const int* wingrid;
    float* pf;
    int e, cellp;
    if (g < pLC) {
        e = g;
        if (e >= g_cnt[0]) return;
        cellp = g_list_lc[e]; feat = fLC; pf = g_pf_lc; wingrid = g_win_lc;
    } else {
        e = g - pLC;
        if (e >= g_cnt[1]) return;
        cellp = g_list_rc[e]; feat = fRC; pf = g_pf_rc; wingrid = g_win_rc;
    }
    int b = cellp / HW, sp = cellp % HW;
    int yp = sp / W, xp = sp % W;
    const int* winc = wingrid + (size_t)b * HWC + (2 * yp) * WC + 2 * xp;
    int w0 = winc[0], w1 = winc[1], w2 = winc[WC], w3 = winc[WC + 1];
    if (lane == 0) {       // zero the cen winner cells (sole owner)
        int2 z = make_int2(0, 0);
        *(int2*)winc = z;
        *(int2*)(winc + WC) = z;
    }
    bool full = (w0 > 0) && (w1 > 0) && (w2 > 0) && (w3 > 0);
#pragma unroll
    for (int h = 0; h < 2; h++) {
        int c = lane + 32 * h;
        float m = full ? -FLT_MAX : 0.0f;
        if (w0 > 0) m = fmaxf(m, __ldg(&feat[(size_t)(w0 - 1) * CH + c]));
        if (w1 > 0) m = fmaxf(m, __ldg(&feat[(size_t)(w1 - 1) * CH + c]));
        if (w2 > 0) m = fmaxf(m, __ldg(&feat[(size_t)(w2 - 1) * CH + c]));
        if (w3 > 0) m = fmaxf(m, __ldg(&feat[(size_t)(w3 - 1) * CH + c]));
        pf[(size_t)e * CH + c] = m;
    }
}

// shared body: one thread = (kind-pair half, b, y, x-quad, 32-channel chunk)
__device__ __forceinline__ void fused_body(int kind, int u,
                                           const float4* __restrict__ f4,
                                           const int* __restrict__ win,
                                           float* __restrict__ out) {
    int x4 = u % XQ; u /= XQ;
    int chunk = u % NCHUNK; u /= NCHUNK;
    int y = u % H;
    int b = u / H;
    int s = y * W + 4 * x4;

    const size_t GRID = (size_t)CH * HW;
    const size_t OUT_R = (size_t)BATCH * GRID;
    const size_t OUT_CAT = 2 * OUT_R;
    const float4 z4 = make_float4(0.f, 0.f, 0.f, 0.f);

    size_t choff = (size_t)(chunk * 32) * HW + s;
    float* cat = out + OUT_CAT + (size_t)b * 4 * GRID;
    float* o1;
    float* o2 = nullptr;
    if (kind == 0) {
        o1 = out + (size_t)b * GRID + choff;
        o2 = cat + choff;
    } else if (kind == 1) {
        o1 = out + OUT_R + (size_t)b * GRID + choff;
        o2 = cat + (size_t)2 * CH * HW + choff;
    } else if (kind == 2) {
        o1 = cat + (size_t)CH * HW + choff;
    } else {
        o1 = cat + (size_t)3 * CH * HW + choff;
    }

    int4 w = *(const int4*)(win + b * HW + s);
    bool any = (w.x | w.y | w.z | w.w) != 0;
    const float4* f4b = f4 - 16;   // values are idx+1

#pragma unroll
    for (int sub = 0; sub < 8; sub++) {
        float4 c0 = z4, c1 = z4, c2 = z4, c3 = z4;
        if (any) {
            int fo = chunk * 8 + sub;
            if (w.x > 0) c0 = __ldg(&f4b[(size_t)w.x * 16 + fo]);
            if (w.y > 0) c1 = __ldg(&f4b[(size_t)w.y * 16 + fo]);
            if (w.z > 0) c2 = __ldg(&f4b[(size_t)w.z * 16 + fo]);
            if (w.w > 0) c3 = __ldg(&f4b[(size_t)w.w * 16 + fo]);
        }
        float4 v0 = make_float4(c0.x, c1.x, c2.x, c3.x);
        float4 v1 = make_float4(c0.y, c1.y, c2.y, c3.y);
        float4 v2 = make_float4(c0.z, c1.z, c2.z, c3.z);
        float4 v3 = make_float4(c0.w, c1.w, c2.w, c3.w);
        size_t co = (size_t)(sub * 4) * HW;
        __stcs((float4*)(o1 + co), v0);
        __stcs((float4*)(o1 + co + HW), v1);
        __stcs((float4*)(o1 + co + 2 * (size_t)HW), v2);
        __stcs((float4*)(o1 + co + 3 * (size_t)HW), v3);
        if (o2) {
            __stcs((float4*)(o2 + co), v0);
            __stcs((float4*)(o2 + co + HW), v1);
            __stcs((float4*)(o2 + co + 2 * (size_t)HW), v2);
            __stcs((float4*)(o2 + co + 3 * (size_t)HW), v3);
        }
    }
}

__global__ void __launch_bounds__(256)
fused_LR(const float4* __restrict__ fL4, const float4* __restrict__ fR4,
         float* __restrict__ out) {
    int t = blockIdx.x * blockDim.x + threadIdx.x;
    int kind = t / PERKIND;           // 0 or 1; uniform per block
    fused_body(kind, t % PERKIND, kind == 0 ? fL4 : fR4,
               kind == 0 ? g_win_l : g_win_r, out);
}

__global__ void __launch_bounds__(256)
fused_cen(float* __restrict__ out) {
    int t = blockIdx.x * blockDim.x + threadIdx.x;
    int kind = 2 + t / PERKIND;       // 2 or 3; uniform per block
    fused_body(kind, t % PERKIND,
               kind == 2 ? (const float4*)g_pf_lc : (const float4*)g_pf_rc,
               kind == 2 ? g_pwin_lc : g_pwin_rc, out);
}

// zero the 480 winner grids (runs after fused_LR, overlaps fused_cen tail)
__global__ void cleanup_LR(const int* __restrict__ cL, int pL,
                           const int* __restrict__ cR, int pR) {
    int i = blockIdx.x * blockDim.x + threadIdx.x;
    if (i < pL) {
        int4 c = __ldg((const int4*)(cL + 4 * i));
        g_win_l[c.x * HW + c.z * W + c.w] = 0;
    } else if (i < pL + pR) {
        int j = i - pL;
        int4 c = __ldg((const int4*)(cR + 4 * j));
        g_win_r[c.x * HW + c.z * W + c.w] = 0;
    }
}

// zero pooled winner grids + counters (after fused_cen)
__global__ void cleanup_cen(const int* __restrict__ cLC, int pLC,
                            const int* __restrict__ cRC, int pRC) {
    int i = blockIdx.x * blockDim.x + threadIdx.x;
    if (i == 0) { g_cnt[0] = 0; g_cnt[1] = 0; }
    if (i < pLC) {
        int4 c = __ldg((const int4*)(cLC + 4 * i));
        g_pwin_lc[c.x * HW + (c.z >> 1) * W + (c.w >> 1)] = 0;
    } else if (i < pLC + pRC) {
        int j = i - pLC;
        int4 c = __ldg((const int4*)(cRC + 4 * j));
        g_pwin_rc[c.x * HW + (c.z >> 1) * W + (c.w >> 1)] = 0;
    }
}

extern "C" void kernel_launch(void* const* d_in, const int* in_sizes, int n_in,
                              void* d_out, int out_size) {
    const float* fRC = (const float*)d_in[0];
    const int*   cRC = (const int*)d_in[1];
    const float* fLC = (const float*)d_in[2];
    const int*   cLC = (const int*)d_in[3];
    const float* fL  = (const float*)d_in[4];
    const int*   cL  = (const int*)d_in[5];
    const float* fR  = (const float*)d_in[6];
    const int*   cR  = (const int*)d_in[7];
    float* out = (float*)d_out;

    int pRC = in_sizes[1] / 4;
    int pLC = in_sizes[3] / 4;
    int pL  = in_sizes[5] / 4;
    int pR  = in_sizes[7] / 4;
    int PT = pL + pR + pLC + pRC;

    // fork-join: side stream runs pool_feat+fused_cen under fused_LR.
    // Stream/event creation is host-only (runs during capture, not replay).
    cudaStream_t s1;
    cudaStreamCreateWithFlags(&s1, cudaStreamNonBlocking);
    cudaEvent_t e0, e1;
    cudaEventCreateWithFlags(&e0, cudaEventDisableTiming);
    cudaEventCreateWithFlags(&e1, cudaEventDisableTiming);

    scatter_all<<<(PT + 255) / 256, 256>>>(cL, pL, cR, pR, cLC, pLC, cRC, pRC);
    cudaEventRecord(e0, 0);
    cudaStreamWaitEvent(s1, e0, 0);

    int pw = pLC + pRC;  // upper bound on occupied pooled cells (both kinds)
    pool_feat<<<(pw * 32 + 255) / 256, 256, 0, s1>>>(fLC, fRC, pLC);
    fused_cen<<<2 * PERKIND / 256, 256, 0, s1>>>(out);
    cudaEventRecord(e1, s1);

    fused_LR<<<2 * PERKIND / 256, 256>>>((const float4*)fL, (const float4*)fR, out);
    cleanup_LR<<<(pL + pR + 255) / 256, 256>>>(cL, pL, cR, pR);

    cudaStreamWaitEvent(0, e1, 0);
    cleanup_cen<<<(pLC + pRC + 255) / 256, 256>>>(cLC, pLC, cRC, pRC);

    cudaEventDestroy(e0);
    cudaEventDestroy(e1);
    cudaStreamDestroy(s1);
}

// round 9
// speedup vs baseline: 1.2585x; 1.0023x over previous
#include <cuda_runtime.h>
#include <float.h>

#define BATCH 2
#define CH 64
#define H 480
#define W 480
#define HW (H * W)            // 230400
#define HC 960
#define WC 960
#define HWC (HC * WC)         // 921600
#define XQ (W / 4)            // 120
#define NCHUNK 2
#define PERKIND (BATCH * NCHUNK * H * XQ)   // 230400
#define LIST_MAX 32768

// ---------------- device scratch (zero at load; each call restores the
// all-zero state: pool_feat zeroes cen winner cells, cleanup_* the rest) ----
// Encoding: winner grids store (point_idx + 1); 0 = empty.
//           pooled grids store (slot + 1);      0 = empty.
__device__ int   g_win_l[BATCH * HW];
__device__ int   g_win_r[BATCH * HW];
__device__ int   g_win_lc[BATCH * HWC];
__device__ int   g_win_rc[BATCH * HWC];
__device__ int   g_pwin_lc[BATCH * HW];
__device__ int   g_pwin_rc[BATCH * HW];
__device__ int   g_list_lc[LIST_MAX];
__device__ int   g_list_rc[LIST_MAX];
__device__ int   g_cnt[2];
__device__ float g_pf_lc[LIST_MAX * CH];     // pooled 64-ch features, compact
__device__ float g_pf_rc[LIST_MAX * CH];

#define CLAIM_TAG 0x7FFFFFFF

// last point index wins == JAX sequential .set semantics
__global__ void scatter_LR(const int* __restrict__ cL, int pL,
                           const int* __restrict__ cR, int pR) {
    int i = blockIdx.x * blockDim.x + threadIdx.x;
    if (i < pL) {
        int4 c = __ldg((const int4*)(cL + 4 * i));
        atomicMax(&g_win_l[c.x * HW + c.z * W + c.w], i + 1);
    } else if (i < pL + pR) {
        int j = i - pL;
        int4 c = __ldg((const int4*)(cR + 4 * j));
        atomicMax(&g_win_r[c.x * HW + c.z * W + c.w], j + 1);
    }
}

__global__ void scatter_cen(const int* __restrict__ cLC, int pLC,
                            const int* __restrict__ cRC, int pRC) {
    int i = blockIdx.x * blockDim.x + threadIdx.x;
    if (i < pLC) {
        int4 c = __ldg((const int4*)(cLC + 4 * i));
        atomicMax(&g_win_lc[c.x * HWC + c.z * WC + c.w], i + 1);
        int cellp = c.x * HW + (c.z >> 1) * W + (c.w >> 1);
        if (atomicCAS(&g_pwin_lc[cellp], 0, CLAIM_TAG) == 0) {
            int e = atomicAdd(&g_cnt[0], 1);
            g_list_lc[e] = cellp;
            g_pwin_lc[cellp] = e + 1;
        }
    } else if (i < pLC + pRC) {
        int j = i - pLC;
        int4 c = __ldg((const int4*)(cRC + 4 * j));
        atomicMax(&g_win_rc[c.x * HWC + c.z * WC + c.w], j + 1);
        int cellp = c.x * HW + (c.z >> 1) * W + (c.w >> 1);
        if (atomicCAS(&g_pwin_rc[cellp], 0, CLAIM_TAG) == 0) {
            int e = atomicAdd(&g_cnt[1], 1);
            g_list_rc[e] = cellp;
            g_pwin_rc[cellp] = e + 1;
        }
    }
}

// one warp per occupied pooled cell: resolve 2x2 max over 64 channels.
// Pool windows partition the cen grid; this warp solely owns its 4 winner
// cells and zeroes them (cen winner-grid cleanup folded in).
__global__ void pool_feat(const float* __restrict__ fLC,
                          const float* __restrict__ fRC, int pLC) {
    int g = (blockIdx.x * blockDim.x + threadIdx.x) >> 5;
    int lane = threadIdx.x & 31;
    const float* feat;
    const int* wingrid;
    float* pf;
    int e, cellp;
    if (g < pLC) {
        e = g;
        if (e >= g_cnt[0]) return;
        cellp = g_list_lc[e]; feat = fLC; pf = g_pf_lc; wingrid = g_win_lc;
    } else {
        e = g - pLC;
        if (e >= g_cnt[1]) return;
        cellp = g_list_rc[e]; feat = fRC; pf = g_pf_rc; wingrid = g_win_rc;
    }
    int b = cellp / HW, sp = cellp % HW;
    int yp = sp / W, xp = sp % W;
    const int* winc = wingrid + (size_t)b * HWC + (2 * yp) * WC + 2 * xp;
    int w0 = winc[0], w1 = winc[1], w2 = winc[WC], w3 = winc[WC + 1];
    if (lane == 0) {       // zero the cen winner cells (sole owner)
        int2 z = make_int2(0, 0);
        *(int2*)winc = z;
        *(int2*)(winc + WC) = z;
    }
    bool full = (w0 > 0) && (w1 > 0) && (w2 > 0) && (w3 > 0);
#pragma unroll
    for (int h = 0; h < 2; h++) {
        int c = lane + 32 * h;
        float m = full ? -FLT_MAX : 0.0f;
        if (w0 > 0) m = fmaxf(m, __ldg(&feat[(size_t)(w0 - 1) * CH + c]));
        if (w1 > 0) m = fmaxf(m, __ldg(&feat[(size_t)(w1 - 1) * CH + c]));
        if (w2 > 0) m = fmaxf(m, __ldg(&feat[(size_t)(w2 - 1) * CH + c]));
        if (w3 > 0) m = fmaxf(m, __ldg(&feat[(size_t)(w3 - 1) * CH + c]));
        pf[(size_t)e * CH + c] = m;
    }
}

// shared body: one thread = (kind, b, y, x-quad, 32-channel chunk)
__device__ __forceinline__ void fused_body(int kind, int u,
                                           const float4* __restrict__ f4,
                                           const int* __restrict__ win,
                                           float* __restrict__ out) {
    int x4 = u % XQ; u /= XQ;
    int chunk = u % NCHUNK; u /= NCHUNK;
    int y = u % H;
    int b = u / H;
    int s = y * W + 4 * x4;

    const size_t GRID = (size_t)CH * HW;
    const size_t OUT_R = (size_t)BATCH * GRID;
    const size_t OUT_CAT = 2 * OUT_R;
    const float4 z4 = make_float4(0.f, 0.f, 0.f, 0.f);

    size_t choff = (size_t)(chunk * 32) * HW + s;
    float* cat = out + OUT_CAT + (size_t)b * 4 * GRID;
    float* o1;
    float* o2 = nullptr;
    if (kind == 0) {
        o1 = out + (size_t)b * GRID + choff;
        o2 = cat + choff;
    } else if (kind == 1) {
        o1 = out + OUT_R + (size_t)b * GRID + choff;
        o2 = cat + (size_t)2 * CH * HW + choff;
    } else if (kind == 2) {
        o1 = cat + (size_t)CH * HW + choff;
    } else {
        o1 = cat + (size_t)3 * CH * HW + choff;
    }

    int4 w = *(const int4*)(win + b * HW + s);
    bool any = (w.x | w.y | w.z | w.w) != 0;
    const float4* f4b = f4 - 16;   // values are idx+1

#pragma unroll
    for (int sub = 0; sub < 8; sub++) {
        float4 c0 = z4, c1 = z4, c2 = z4, c3 = z4;
        if (any) {
            int fo = chunk * 8 + sub;
            if (w.x > 0) c0 = __ldg(&f4b[(size_t)w.x * 16 + fo]);
            if (w.y > 0) c1 = __ldg(&f4b[(size_t)w.y * 16 + fo]);
            if (w.z > 0) c2 = __ldg(&f4b[(size_t)w.z * 16 + fo]);
            if (w.w > 0) c3 = __ldg(&f4b[(size_t)w.w * 16 + fo]);
        }
        float4 v0 = make_float4(c0.x, c1.x, c2.x, c3.x);
        float4 v1 = make_float4(c0.y, c1.y, c2.y, c3.y);
        float4 v2 = make_float4(c0.z, c1.z, c2.z, c3.z);
        float4 v3 = make_float4(c0.w, c1.w, c2.w, c3.w);
        size_t co = (size_t)(sub * 4) * HW;
        __stcs((float4*)(o1 + co), v0);
        __stcs((float4*)(o1 + co + HW), v1);
        __stcs((float4*)(o1 + co + 2 * (size_t)HW), v2);
        __stcs((float4*)(o1 + co + 3 * (size_t)HW), v3);
        if (o2) {
            __stcs((float4*)(o2 + co), v0);
            __stcs((float4*)(o2 + co + HW), v1);
            __stcs((float4*)(o2 + co + 2 * (size_t)HW), v2);
            __stcs((float4*)(o2 + co + 3 * (size_t)HW), v3);
        }
    }
}

__global__ void __launch_bounds__(256)
fused_LR(const float4* __restrict__ fL4, const float4* __restrict__ fR4,
         float* __restrict__ out) {
    int t = blockIdx.x * blockDim.x + threadIdx.x;
    int kind = t / PERKIND;           // 0 or 1; uniform per block
    fused_body(kind, t % PERKIND, kind == 0 ? fL4 : fR4,
               kind == 0 ? g_win_l : g_win_r, out);
}

__global__ void __launch_bounds__(256)
fused_cen(float* __restrict__ out) {
    int t = blockIdx.x * blockDim.x + threadIdx.x;
    int kind = 2 + t / PERKIND;       // 2 or 3; uniform per block
    fused_body(kind, t % PERKIND,
               kind == 2 ? (const float4*)g_pf_lc : (const float4*)g_pf_rc,
               kind == 2 ? g_pwin_lc : g_pwin_rc, out);
}

// zero the 480 winner grids (after fused_LR; overlaps fused_cen)
__global__ void cleanup_LR(const int* __restrict__ cL, int pL,
                           const int* __restrict__ cR, int pR) {
    int i = blockIdx.x * blockDim.x + threadIdx.x;
    if (i < pL) {
        int4 c = __ldg((const int4*)(cL + 4 * i));
        g_win_l[c.x * HW + c.z * W + c.w] = 0;
    } else if (i < pL + pR) {
        int j = i - pL;
        int4 c = __ldg((const int4*)(cR + 4 * j));
        g_win_r[c.x * HW + c.z * W + c.w] = 0;
    }
}

// zero pooled winner grids + counters (after fused_cen; overlaps fused_LR)
__global__ void cleanup_cen(const int* __restrict__ cLC, int pLC,
                            const int* __restrict__ cRC, int pRC) {
    int i = blockIdx.x * blockDim.x + threadIdx.x;
    if (i == 0) { g_cnt[0] = 0; g_cnt[1] = 0; }
    if (i < pLC) {
        int4 c = __ldg((const int4*)(cLC + 4 * i));
        g_pwin_lc[c.x * HW + (c.z >> 1) * W + (c.w >> 1)] = 0;
    } else if (i < pLC + pRC) {
        int j = i - pLC;
        int4 c = __ldg((const int4*)(cRC + 4 * j));
        g_pwin_rc[c.x * HW + (c.z >> 1) * W + (c.w >> 1)] = 0;
    }
}

extern "C" void kernel_launch(void* const* d_in, const int* in_sizes, int n_in,
                              void* d_out, int out_size) {
    const float* fRC = (const float*)d_in[0];
    const int*   cRC = (const int*)d_in[1];
    const float* fLC = (const float*)d_in[2];
    const int*   cLC = (const int*)d_in[3];
    const float* fL  = (const float*)d_in[4];
    const int*   cL  = (const int*)d_in[5];
    const float* fR  = (const float*)d_in[6];
    const int*   cR  = (const int*)d_in[7];
    float* out = (float*)d_out;

    int pRC = in_sizes[1] / 4;
    int pLC = in_sizes[3] / 4;
    int pL  = in_sizes[5] / 4;
    int pR  = in_sizes[7] / 4;

    // Two dependency chains, fork-join around stream 0 for graph capture.
    // Stream/event creation is host-only (capture-time, not replay-time).
    cudaStream_t s1;
    cudaStreamCreateWithFlags(&s1, cudaStreamNonBlocking);
    cudaEvent_t e_fork, e_join;
    cudaEventCreateWithFlags(&e_fork, cudaEventDisableTiming);
    cudaEventCreateWithFlags(&e_join, cudaEventDisableTiming);

    cudaEventRecord(e_fork, 0);
    cudaStreamWaitEvent(s1, e_fork, 0);

    // side chain (longer): cen scatter -> pool -> fused_cen -> cleanup_cen
    scatter_cen<<<(pLC + pRC + 255) / 256, 256, 0, s1>>>(cLC, pLC, cRC, pRC);
    int pw = pLC + pRC;  // upper bound on occupied pooled cells (both kinds)
    pool_feat<<<(pw * 32 + 255) / 256, 256, 0, s1>>>(fLC, fRC, pLC);
    fused_cen<<<2 * PERKIND / 256, 256, 0, s1>>>(out);
    cleanup_cen<<<(pLC + pRC + 255) / 256, 256, 0, s1>>>(cLC, pLC, cRC, pRC);
    cudaEventRecord(e_join, s1);

    // main chain: LR scatter -> fused_LR -> cleanup_LR
    scatter_LR<<<(pL + pR + 255) / 256, 256>>>(cL, pL, cR, pR);
    fused_LR<<<2 * PERKIND / 256, 256>>>((const float4*)fL, (const float4*)fR, out);
    cleanup_LR<<<(pL + pR + 255) / 256, 256>>>(cL, pL, cR, pR);

    cudaStreamWaitEvent(0, e_join, 0);

    cudaEventDestroy(e_fork);
    cudaEventDestroy(e_join);
    cudaStreamDestroy(s1);
}

// round 10
// speedup vs baseline: 1.3110x; 1.0417x over previous
#include <cuda_runtime.h>
#include <float.h>

#define BATCH 2
#define CH 64
#define H 480
#define W 480
#define HW (H * W)            // 230400
#define HC 960
#define WC 960
#define HWC (HC * WC)         // 921600
#define NQUAD (BATCH * H * (W / 4))   // 115200 quads per kind
#define WARPS_PER_KIND (NQUAD / 16)   // 7200
#define QUADS_PER_B (H * (W / 4))     // 57600
#define LIST_MAX 32768

// ---------------- device scratch (zero at load; each call restores the
// all-zero state: pool_feat zeroes cen winner cells; the fused kernels zero
// the 480 winner / pooled grids as they consume them) -----------------------
// Encoding: winner grids store (point_idx + 1); 0 = empty.
//           pooled grids store (slot + 1);      0 = empty.
__device__ int   g_win_l[BATCH * HW];
__device__ int   g_win_r[BATCH * HW];
__device__ int   g_win_lc[BATCH * HWC];
__device__ int   g_win_rc[BATCH * HWC];
__device__ int   g_pwin_lc[BATCH * HW];
__device__ int   g_pwin_rc[BATCH * HW];
__device__ int   g_list_lc[LIST_MAX];
__device__ int   g_list_rc[LIST_MAX];
__device__ int   g_cnt[2];
__device__ float g_pf_lc[LIST_MAX * CH];     // pooled 64-ch features, compact
__device__ float g_pf_rc[LIST_MAX * CH];

#define CLAIM_TAG 0x7FFFFFFF

// last point index wins == JAX sequential .set semantics
__global__ void scatter_LR(const int* __restrict__ cL, int pL,
                           const int* __restrict__ cR, int pR) {
    int i = blockIdx.x * blockDim.x + threadIdx.x;
    if (i < pL) {
        int4 c = __ldg((const int4*)(cL + 4 * i));
        atomicMax(&g_win_l[c.x * HW + c.z * W + c.w], i + 1);
    } else if (i < pL + pR) {
        int j = i - pL;
        int4 c = __ldg((const int4*)(cR + 4 * j));
        atomicMax(&g_win_r[c.x * HW + c.z * W + c.w], j + 1);
    }
}

__global__ void scatter_cen(const int* __restrict__ cLC, int pLC,
                            const int* __restrict__ cRC, int pRC) {
    int i = blockIdx.x * blockDim.x + threadIdx.x;
    if (i < pLC) {
        int4 c = __ldg((const int4*)(cLC + 4 * i));
        atomicMax(&g_win_lc[c.x * HWC + c.z * WC + c.w], i + 1);
        int cellp = c.x * HW + (c.z >> 1) * W + (c.w >> 1);
        if (atomicCAS(&g_pwin_lc[cellp], 0, CLAIM_TAG) == 0) {
            int e = atomicAdd(&g_cnt[0], 1);
            g_list_lc[e] = cellp;
            g_pwin_lc[cellp] = e + 1;
        }
    } else if (i < pLC + pRC) {
        int j = i - pLC;
        int4 c = __ldg((const int4*)(cRC + 4 * j));
        atomicMax(&g_win_rc[c.x * HWC + c.z * WC + c.w], j + 1);
        int cellp = c.x * HW + (c.z >> 1) * W + (c.w >> 1);
        if (atomicCAS(&g_pwin_rc[cellp], 0, CLAIM_TAG) == 0) {
            int e = atomicAdd(&g_cnt[1], 1);
            g_list_rc[e] = cellp;
            g_pwin_rc[cellp] = e + 1;
        }
    }
}

// one warp per occupied pooled cell: resolve 2x2 max over 64 channels.
// Pool windows partition the cen grid; this warp solely owns its 4 winner
// cells and zeroes them (cen winner-grid cleanup folded in).
__global__ void pool_feat(const float* __restrict__ fLC,
                          const float* __restrict__ fRC, int pLC) {
    int g = (blockIdx.x * blockDim.x + threadIdx.x) >> 5;
    int lane = threadIdx.x & 31;
    const float* feat;
    const int* wingrid;
    float* pf;
    int e, cellp;
    if (g < pLC) {
        e = g;
        if (e >= g_cnt[0]) return;
        cellp = g_list_lc[e]; feat = fLC; pf = g_pf_lc; wingrid = g_win_lc;
    } else {
        e = g - pLC;
        if (e >= g_cnt[1]) return;
        cellp = g_list_rc[e]; feat = fRC; pf = g_pf_rc; wingrid = g_win_rc;
    }
    int b = cellp / HW, sp = cellp % HW;
    int yp = sp / W, xp = sp % W;
    const int* winc = wingrid + (size_t)b * HWC + (2 * yp) * WC + 2 * xp;
    int w0 = winc[0], w1 = winc[1], w2 = winc[WC], w3 = winc[WC + 1];
    if (lane == 0) {       // zero the cen winner cells (sole owner)
        int2 z = make_int2(0, 0);
        *(int2*)winc = z;
        *(int2*)(winc + WC) = z;
    }
    bool full = (w0 > 0) && (w1 > 0) && (w2 > 0) && (w3 > 0);
#pragma unroll
    for (int h = 0; h < 2; h++) {
        int c = lane + 32 * h;
        float m = full ? -FLT_MAX : 0.0f;
        if (w0 > 0) m = fmaxf(m, __ldg(&feat[(size_t)(w0 - 1) * CH + c]));
        if (w1 > 0) m = fmaxf(m, __ldg(&feat[(size_t)(w1 - 1) * CH + c]));
        if (w2 > 0) m = fmaxf(m, __ldg(&feat[(size_t)(w2 - 1) * CH + c]));
        if (w3 > 0) m = fmaxf(m, __ldg(&feat[(size_t)(w3 - 1) * CH + c]));
        pf[(size_t)e * CH + c] = m;
    }
}

// shared body. Warp layout: lanes 0-15 = chunk 0 of 16 consecutive quads,
// lanes 16-31 = chunk 1 of the SAME quads. After all lanes load the winner
// quad, __syncwarp, then lanes 0-15 zero it (scratch cleanup folded in).
// do_clean: fused kernels own zeroing of their winner grids.
__device__ __forceinline__ void fused_body(int kind, int warp_in_kind,
                                           int lane,
                                           const float4* __restrict__ f4,
                                           int* __restrict__ win,
                                           float* __restrict__ out) {
    int q = warp_in_kind * 16 + (lane & 15);   // quad index within kind
    int chunk = lane >> 4;
    int b = q / QUADS_PER_B;
    int s = (q - b * QUADS_PER_B) * 4;         // contiguous over (y,x4)

    const size_t GRID = (size_t)CH * HW;
    const size_t OUT_R = (size_t)BATCH * GRID;
    const size_t OUT_CAT = 2 * OUT_R;
    const float4 z4 = make_float4(0.f, 0.f, 0.f, 0.f);

    size_t choff = (size_t)(chunk * 32) * HW + s;
    float* cat = out + OUT_CAT + (size_t)b * 4 * GRID;
    float* o1;
    float* o2 = nullptr;
    if (kind == 0) {
        o1 = out + (size_t)b * GRID + choff;
        o2 = cat + choff;
    } else if (kind == 1) {
        o1 = out + OUT_R + (size_t)b * GRID + choff;
        o2 = cat + (size_t)2 * CH * HW + choff;
    } else if (kind == 2) {
        o1 = cat + (size_t)CH * HW + choff;
    } else {
        o1 = cat + (size_t)3 * CH * HW + choff;
    }

    int4* wp = (int4*)(win + b * HW + s);
    int4 w = *wp;
    bool any = (w.x | w.y | w.z | w.w) != 0;
    __syncwarp();                               // all lanes have loaded
    if (any && chunk == 0) *wp = make_int4(0, 0, 0, 0);  // restore zero state
    const float4* f4b = f4 - 16;                // values are idx+1

#pragma unroll
    for (int sub = 0; sub < 8; sub++) {
        float4 c0 = z4, c1 = z4, c2 = z4, c3 = z4;
        if (any) {
            int fo = chunk * 8 + sub;
            if (w.x > 0) c0 = __ldg(&f4b[(size_t)w.x * 16 + fo]);
            if (w.y > 0) c1 = __ldg(&f4b[(size_t)w.y * 16 + fo]);
            if (w.z > 0) c2 = __ldg(&f4b[(size_t)w.z * 16 + fo]);
            if (w.w > 0) c3 = __ldg(&f4b[(size_t)w.w * 16 + fo]);
        }
        float4 v0 = make_float4(c0.x, c1.x, c2.x, c3.x);
        float4 v1 = make_float4(c0.y, c1.y, c2.y, c3.y);
        float4 v2 = make_float4(c0.z, c1.z, c2.z, c3.z);
        float4 v3 = make_float4(c0.w, c1.w, c2.w, c3.w);
        size_t co = (size_t)(sub * 4) * HW;
        __stcs((float4*)(o1 + co), v0);
        __stcs((float4*)(o1 + co + HW), v1);
        __stcs((float4*)(o1 + co + 2 * (size_t)HW), v2);
        __stcs((float4*)(o1 + co + 3 * (size_t)HW), v3);
        if (o2) {
            __stcs((float4*)(o2 + co), v0);
            __stcs((float4*)(o2 + co + HW), v1);
            __stcs((float4*)(o2 + co + 2 * (size_t)HW), v2);
            __stcs((float4*)(o2 + co + 3 * (size_t)HW), v3);
        }
    }
}

__global__ void __launch_bounds__(256)
fused_LR(const float4* __restrict__ fL4, const float4* __restrict__ fR4,
         float* __restrict__ out) {
    int t = blockIdx.x * blockDim.x + threadIdx.x;
    int gw = t >> 5, lane = t & 31;
    int kind = gw / WARPS_PER_KIND;            // 0 or 1
    fused_body(kind, gw % WARPS_PER_KIND, lane,
               kind == 0 ? fL4 : fR4,
               kind == 0 ? g_win_l : g_win_r, out);
}

__global__ void __launch_bounds__(256)
fused_cen(float* __restrict__ out) {
    int t = blockIdx.x * blockDim.x + threadIdx.x;
    if (t == 0) { g_cnt[0] = 0; g_cnt[1] = 0; }  // pool_feat already consumed
    int gw = t >> 5, lane = t & 31;
    int kind = 2 + gw / WARPS_PER_KIND;        // 2 or 3
    fused_body(kind, gw % WARPS_PER_KIND, lane,
               kind == 2 ? (const float4*)g_pf_lc : (const float4*)g_pf_rc,
               kind == 2 ? g_pwin_lc : g_pwin_rc, out);
}

extern "C" void kernel_launch(void* const* d_in, const int* in_sizes, int n_in,
                              void* d_out, int out_size) {
    const float* fRC = (const float*)d_in[0];
    const int*   cRC = (const int*)d_in[1];
    const float* fLC = (const float*)d_in[2];
    const int*   cLC = (const int*)d_in[3];
    const float* fL  = (const float*)d_in[4];
    const int*   cL  = (const int*)d_in[5];
    const float* fR  = (const float*)d_in[6];
    const int*   cR  = (const int*)d_in[7];
    float* out = (float*)d_out;

    int pRC = in_sizes[1] / 4;
    int pLC = in_sizes[3] / 4;
    int pL  = in_sizes[5] / 4;
    int pR  = in_sizes[7] / 4;

    // Two dependency chains, fork-join around stream 0 for graph capture.
    // Stream/event creation is host-only (capture-time, not replay-time).
    cudaStream_t s1;
    cudaStreamCreateWithFlags(&s1, cudaStreamNonBlocking);
    cudaEvent_t e_fork, e_join;
    cudaEventCreateWithFlags(&e_fork, cudaEventDisableTiming);
    cudaEventCreateWithFlags(&e_join, cudaEventDisableTiming);

    cudaEventRecord(e_fork, 0);
    cudaStreamWaitEvent(s1, e_fork, 0);

    // side chain (longer prologue): cen scatter -> pool -> fused_cen
    scatter_cen<<<(pLC + pRC + 255) / 256, 256, 0, s1>>>(cLC, pLC, cRC, pRC);
    int pw = pLC + pRC;  // upper bound on occupied pooled cells (both kinds)
    pool_feat<<<(pw * 32 + 255) / 256, 256, 0, s1>>>(fLC, fRC, pLC);
    fused_cen<<<2 * WARPS_PER_KIND * 32 / 256, 256, 0, s1>>>(out);
    cudaEventRecord(e_join, s1);

    // main chain: LR scatter -> fused_LR
    scatter_LR<<<(pL + pR + 255) / 256, 256>>>(cL, pL, cR, pR);
    fused_LR<<<2 * WARPS_PER_KIND * 32 / 256, 256>>>((const float4*)fL,
                                                     (const float4*)fR, out);

    cudaStreamWaitEvent(0, e_join, 0);

    cudaEventDestroy(e_fork);
    cudaEventDestroy(e_join);
    cudaStreamDestroy(s1);
}

// round 11
// speedup vs baseline: 1.3138x; 1.0021x over previous
#include <cuda_runtime.h>
#include <float.h>

#define BATCH 2
#define CH 64
#define H 480
#define W 480
#define HW (H * W)            // 230400
#define HC 960
#define WC 960
#define HWC (HC * WC)         // 921600
#define NQUAD (BATCH * H * (W / 4))   // 115200 quads per kind
#define WARPS_PER_KIND (NQUAD / 16)   // 7200
#define QUADS_PER_B (H * (W / 4))     // 57600
#define LIST_MAX 32768

// ---------------- device scratch (zero at load; each call restores the
// all-zero state: pool_feat zeroes cen winner cells; the fused kernels zero
// the 480 winner / pooled grids as they consume them) -----------------------
// Encoding: winner grids store (point_idx + 1); 0 = empty.
//           pooled grids store (slot + 1);      0 = empty.
__device__ int   g_win_l[BATCH * HW];
__device__ int   g_win_r[BATCH * HW];
__device__ int   g_win_lc[BATCH * HWC];
__device__ int   g_win_rc[BATCH * HWC];
__device__ int   g_pwin_lc[BATCH * HW];
__device__ int   g_pwin_rc[BATCH * HW];
__device__ int   g_list_lc[LIST_MAX];
__device__ int   g_list_rc[LIST_MAX];
__device__ int   g_cnt[2];
__device__ float g_pf_lc[LIST_MAX * CH];     // pooled 64-ch features, compact
__device__ float g_pf_rc[LIST_MAX * CH];

#define CLAIM_TAG 0x7FFFFFFF

// last point index wins == JAX sequential .set semantics
__global__ void scatter_LR(const int* __restrict__ cL, int pL,
                           const int* __restrict__ cR, int pR) {
    int i = blockIdx.x * blockDim.x + threadIdx.x;
    if (i < pL) {
        int4 c = __ldg((const int4*)(cL + 4 * i));
        atomicMax(&g_win_l[c.x * HW + c.z * W + c.w], i + 1);
    } else if (i < pL + pR) {
        int j = i - pL;
        int4 c = __ldg((const int4*)(cR + 4 * j));
        atomicMax(&g_win_r[c.x * HW + c.z * W + c.w], j + 1);
    }
    cudaTriggerProgrammaticLaunchCompletion();
}

__global__ void scatter_cen(const int* __restrict__ cLC, int pLC,
                            const int* __restrict__ cRC, int pRC) {
    int i = blockIdx.x * blockDim.x + threadIdx.x;
    if (i < pLC) {
        int4 c = __ldg((const int4*)(cLC + 4 * i));
        atomicMax(&g_win_lc[c.x * HWC + c.z * WC + c.w], i + 1);
        int cellp = c.x * HW + (c.z >> 1) * W + (c.w >> 1);
        if (atomicCAS(&g_pwin_lc[cellp], 0, CLAIM_TAG) == 0) {
            int e = atomicAdd(&g_cnt[0], 1);
            g_list_lc[e] = cellp;
            g_pwin_lc[cellp] = e + 1;
        }
    } else if (i < pLC + pRC) {
        int j = i - pLC;
        int4 c = __ldg((const int4*)(cRC + 4 * j));
        atomicMax(&g_win_rc[c.x * HWC + c.z * WC + c.w], j + 1);
        int cellp = c.x * HW + (c.z >> 1) * W + (c.w >> 1);
        if (atomicCAS(&g_pwin_rc[cellp], 0, CLAIM_TAG) == 0) {
            int e = atomicAdd(&g_cnt[1], 1);
            g_list_rc[e] = cellp;
            g_pwin_rc[cellp] = e + 1;
        }
    }
    cudaTriggerProgrammaticLaunchCompletion();
}

// one warp per occupied pooled cell: resolve 2x2 max over 64 channels.
// Pool windows partition the cen grid; this warp solely owns its 4 winner
// cells and zeroes them (cen winner-grid cleanup folded in).
__global__ void pool_feat(const float* __restrict__ fLC,
                          const float* __restrict__ fRC, int pLC) {
    cudaGridDependencySynchronize();            // wait for scatter_cen data
    int g = (blockIdx.x * blockDim.x + threadIdx.x) >> 5;
    int lane = threadIdx.x & 31;
    const float* feat;
    const int* wingrid;
    float* pf;
    int e, cellp;
    bool active = true;
    if (g < pLC) {
        e = g;
        if (e >= g_cnt[0]) active = false;
        cellp = active ? g_list_lc[e] : 0;
        feat = fLC; pf = g_pf_lc; wingrid = g_win_lc;
    } else {
        e = g - pLC;
        if (e >= g_cnt[1]) active = false;
        cellp = active ? g_list_rc[e] : 0;
        feat = fRC; pf = g_pf_rc; wingrid = g_win_rc;
    }
    if (active) {
        int b = cellp / HW, sp = cellp % HW;
        int yp = sp / W, xp = sp % W;
        const int* winc = wingrid + (size_t)b * HWC + (2 * yp) * WC + 2 * xp;
        int w0 = winc[0], w1 = winc[1], w2 = winc[WC], w3 = winc[WC + 1];
        if (lane == 0) {   // zero the cen winner cells (sole owner)
            int2 z = make_int2(0, 0);
            *(int2*)winc = z;
            *(int2*)(winc + WC) = z;
        }
        bool full = (w0 > 0) && (w1 > 0) && (w2 > 0) && (w3 > 0);
#pragma unroll
        for (int h = 0; h < 2; h++) {
            int c = lane + 32 * h;
            float m = full ? -FLT_MAX : 0.0f;
            if (w0 > 0) m = fmaxf(m, __ldg(&feat[(size_t)(w0 - 1) * CH + c]));
            if (w1 > 0) m = fmaxf(m, __ldg(&feat[(size_t)(w1 - 1) * CH + c]));
            if (w2 > 0) m = fmaxf(m, __ldg(&feat[(size_t)(w2 - 1) * CH + c]));
            if (w3 > 0) m = fmaxf(m, __ldg(&feat[(size_t)(w3 - 1) * CH + c]));
            pf[(size_t)e * CH + c] = m;
        }
    }
    cudaTriggerProgrammaticLaunchCompletion();
}

// shared body. Warp layout: lanes 0-15 = chunk 0 of 16 consecutive quads,
// lanes 16-31 = chunk 1 of the SAME quads. After all lanes load the winner
// quad, __syncwarp, then lanes 0-15 zero it (scratch cleanup folded in).
__device__ __forceinline__ void fused_body(int kind, int warp_in_kind,
                                           int lane,
                                           const float4* __restrict__ f4,
                                           int* __restrict__ win,
                                           float* __restrict__ out) {
    int q = warp_in_kind * 16 + (lane & 15);   // quad index within kind
    int chunk = lane >> 4;
    int b = q / QUADS_PER_B;
    int s = (q - b * QUADS_PER_B) * 4;         // contiguous over (y,x4)

    const size_t GRID = (size_t)CH * HW;
    const size_t OUT_R = (size_t)BATCH * GRID;
    const size_t OUT_CAT = 2 * OUT_R;
    const float4 z4 = make_float4(0.f, 0.f, 0.f, 0.f);

    size_t choff = (size_t)(chunk * 32) * HW + s;
    float* cat = out + OUT_CAT + (size_t)b * 4 * GRID;
    float* o1;
    float* o2 = nullptr;
    if (kind == 0) {
        o1 = out + (size_t)b * GRID + choff;
        o2 = cat + choff;
    } else if (kind == 1) {
        o1 = out + OUT_R + (size_t)b * GRID + choff;
        o2 = cat + (size_t)2 * CH * HW + choff;
    } else if (kind == 2) {
        o1 = cat + (size_t)CH * HW + choff;
    } else {
        o1 = cat + (size_t)3 * CH * HW + choff;
    }

    int4* wp = (int4*)(win + b * HW + s);
    int4 w = *wp;
    bool any = (w.x | w.y | w.z | w.w) != 0;
    __syncwarp();                               // all lanes have loaded
    if (any && chunk == 0) *wp = make_int4(0, 0, 0, 0);  // restore zero state
    const float4* f4b = f4 - 16;                // values are idx+1

#pragma unroll
    for (int sub = 0; sub < 8; sub++) {
        float4 c0 = z4, c1 = z4, c2 = z4, c3 = z4;
        if (any) {
            int fo = chunk * 8 + sub;
            if (w.x > 0) c0 = __ldg(&f4b[(size_t)w.x * 16 + fo]);
            if (w.y > 0) c1 = __ldg(&f4b[(size_t)w.y * 16 + fo]);
            if (w.z > 0) c2 = __ldg(&f4b[(size_t)w.z * 16 + fo]);
            if (w.w > 0) c3 = __ldg(&f4b[(size_t)w.w * 16 + fo]);
        }
        float4 v0 = make_float4(c0.x, c1.x, c2.x, c3.x);
        float4 v1 = make_float4(c0.y, c1.y, c2.y, c3.y);
        float4 v2 = make_float4(c0.z, c1.z, c2.z, c3.z);
        float4 v3 = make_float4(c0.w, c1.w, c2.w, c3.w);
        size_t co = (size_t)(sub * 4) * HW;
        __stcs((float4*)(o1 + co), v0);
        __stcs((float4*)(o1 + co + HW), v1);
        __stcs((float4*)(o1 + co + 2 * (size_t)HW), v2);
        __stcs((float4*)(o1 + co + 3 * (size_t)HW), v3);
        if (o2) {
            __stcs((float4*)(o2 + co), v0);
            __stcs((float4*)(o2 + co + HW), v1);
            __stcs((float4*)(o2 + co + 2 * (size_t)HW), v2);
            __stcs((float4*)(o2 + co + 3 * (size_t)HW), v3);
        }
    }
}

__global__ void __launch_bounds__(256)
fused_LR(const float4* __restrict__ fL4, const float4* __restrict__ fR4,
         float* __restrict__ out) {
    int t = blockIdx.x * blockDim.x + threadIdx.x;
    int gw = t >> 5, lane = t & 31;
    int kind = gw / WARPS_PER_KIND;            // 0 or 1
    cudaGridDependencySynchronize();           // wait for scatter_LR data
    fused_body(kind, gw % WARPS_PER_KIND, lane,
               kind == 0 ? fL4 : fR4,
               kind == 0 ? g_win_l : g_win_r, out);
}

__global__ void __launch_bounds__(256)
fused_cen(float* __restrict__ out) {
    int t = blockIdx.x * blockDim.x + threadIdx.x;
    int gw = t >> 5, lane = t & 31;
    int kind = 2 + gw / WARPS_PER_KIND;        // 2 or 3
    cudaGridDependencySynchronize();           // wait for pool_feat data
    if (t == 0) { g_cnt[0] = 0; g_cnt[1] = 0; }  // pool_feat already consumed
    fused_body(kind, gw % WARPS_PER_KIND, lane,
               kind == 2 ? (const float4*)g_pf_lc : (const float4*)g_pf_rc,
               kind == 2 ? g_pwin_lc : g_pwin_rc, out);
}

// helper: launch with PDL (programmatic stream serialization) on a stream
template <typename... Args>
static void launch_pdl(void (*kern)(Args...), dim3 grid, dim3 block,
                       cudaStream_t stream, Args... args) {
    cudaLaunchConfig_t cfg = {};
    cfg.gridDim = grid;
    cfg.blockDim = block;
    cfg.dynamicSmemBytes = 0;
    cfg.stream = stream;
    cudaLaunchAttribute attr[1];
    attr[0].id = cudaLaunchAttributeProgrammaticStreamSerialization;
    attr[0].val.programmaticStreamSerializationAllowed = 1;
    cfg.attrs = attr;
    cfg.numAttrs = 1;
    cudaLaunchKernelEx(&cfg, kern, args...);
}

extern "C" void kernel_launch(void* const* d_in, const int* in_sizes, int n_in,
                              void* d_out, int out_size) {
    const float* fRC = (const float*)d_in[0];
    const int*   cRC = (const int*)d_in[1];
    const float* fLC = (const float*)d_in[2];
    const int*   cLC = (const int*)d_in[3];
    const float* fL  = (const float*)d_in[4];
    const int*   cL  = (const int*)d_in[5];
    const float* fR  = (const float*)d_in[6];
    const int*   cR  = (const int*)d_in[7];
    float* out = (float*)d_out;

    int pRC = in_sizes[1] / 4;
    int pLC = in_sizes[3] / 4;
    int pL  = in_sizes[5] / 4;
    int pR  = in_sizes[7] / 4;

    // Two dependency chains, fork-join around stream 0 for graph capture.
    // Stream/event creation is host-only (capture-time, not replay-time).
    cudaStream_t s1;
    cudaStreamCreateWithFlags(&s1, cudaStreamNonBlocking);
    cudaEvent_t e_fork, e_join;
    cudaEventCreateWithFlags(&e_fork, cudaEventDisableTiming);
    cudaEventCreateWithFlags(&e_join, cudaEventDisableTiming);

    cudaEventRecord(e_fork, 0);
    cudaStreamWaitEvent(s1, e_fork, 0);

    // side chain: cen scatter -> pool -> fused_cen (PDL between links)
    scatter_cen<<<(pLC + pRC + 255) / 256, 256, 0, s1>>>(cLC, pLC, cRC, pRC);
    int pw = pLC + pRC;  // upper bound on occupied pooled cells (both kinds)
    launch_pdl(pool_feat, dim3((pw * 32 + 255) / 256), dim3(256), s1,
               fLC, fRC, pLC);
    launch_pdl(fused_cen, dim3(2 * WARPS_PER_KIND * 32 / 256), dim3(256), s1,
               out);
    cudaEventRecord(e_join, s1);

    // main chain: LR scatter -> fused_LR (PDL link)
    scatter_LR<<<(pL + pR + 255) / 256, 256>>>(cL, pL, cR, pR);
    launch_pdl(fused_LR, dim3(2 * WARPS_PER_KIND * 32 / 256), dim3(256),
               (cudaStream_t)0, (const float4*)fL, (const float4*)fR, out);

    cudaStreamWaitEvent(0, e_join, 0);

    cudaEventDestroy(e_fork);
    cudaEventDestroy(e_join);
    cudaStreamDestroy(s1);
}